// round 1
// baseline (speedup 1.0000x reference)
#include <cuda_runtime.h>
#include <cuda_bf16.h>
#include <math.h>

// ---------------- problem constants ----------------
#define DIMX     512
#define INTER    64
#define NSH      2
#define NROUTED  64
#define NEXP     66          // NSH + NROUTED
#define TOPK     6
#define KSLOT    8           // TOPK + NSH
#define NTOK     1024        // B*T
#define NSLOT    (NTOK * KSLOT)   // 8192
#define TILE_M   32
#define MAXTILES 320

// ---------------- device scratch (no allocs allowed) ----------------
__device__ int   g_eidx[NSLOT];        // expert id per token-slot
__device__ float g_wt[NSLOT];          // combine weight per token-slot
__device__ int   g_counts[NEXP];
__device__ int   g_fill[NEXP];
__device__ int   g_offsets[NEXP + 1];
__device__ int   g_perm[NSLOT];        // token-slot ids grouped by expert
__device__ int4  g_tiles[MAXTILES];    // (expert, segStart, len, 0)
__device__ int   g_ntiles;
__device__ float g_slot_out[(size_t)NSLOT * DIMX];  // 16 MB scratch

// ---------------- kernel 0: zero counters ----------------
__global__ void zero_kernel() {
    int t = threadIdx.x;
    if (t < NEXP) { g_counts[t] = 0; g_fill[t] = 0; }
}

// ---------------- kernel 1: gate (scores GEMM + softmax + topk) ----------------
// grid 32 blocks x 256 threads, 32 tokens per block
__global__ __launch_bounds__(256) void gate_kernel(
    const float* __restrict__ x, const float* __restrict__ gw,
    const float* __restrict__ bias)
{
    __shared__ float Xs[32][32];
    __shared__ float Gs[32][65];
    __shared__ float S[32][66];

    int tid  = threadIdx.x;
    int tok0 = blockIdx.x * 32;
    int tg   = tid >> 5;       // warp id: 4 tokens each
    int lane = tid & 31;

    float acc[4][2] = {};

    for (int k0 = 0; k0 < DIMX; k0 += 32) {
        // load X tile [32 tok][32 k]
        {
            int r = tid >> 3;
            int c = (tid & 7) * 4;
            float4 v = *reinterpret_cast<const float4*>(&x[(size_t)(tok0 + r) * DIMX + k0 + c]);
            Xs[r][c] = v.x; Xs[r][c+1] = v.y; Xs[r][c+2] = v.z; Xs[r][c+3] = v.w;
        }
        // load G^T tile [32 k][64 e]
        {
            int e  = tid >> 2;
            int kk = (tid & 3) * 8;
            float4 a = *reinterpret_cast<const float4*>(&gw[(size_t)e * DIMX + k0 + kk]);
            float4 b = *reinterpret_cast<const float4*>(&gw[(size_t)e * DIMX + k0 + kk + 4]);
            Gs[kk+0][e] = a.x; Gs[kk+1][e] = a.y; Gs[kk+2][e] = a.z; Gs[kk+3][e] = a.w;
            Gs[kk+4][e] = b.x; Gs[kk+5][e] = b.y; Gs[kk+6][e] = b.z; Gs[kk+7][e] = b.w;
        }
        __syncthreads();
        #pragma unroll
        for (int kk = 0; kk < 32; kk++) {
            float g0 = Gs[kk][lane], g1 = Gs[kk][lane + 32];
            #pragma unroll
            for (int i = 0; i < 4; i++) {
                float xv = Xs[tg * 4 + i][kk];
                acc[i][0] = fmaf(xv, g0, acc[i][0]);
                acc[i][1] = fmaf(xv, g1, acc[i][1]);
            }
        }
        __syncthreads();
    }
    #pragma unroll
    for (int i = 0; i < 4; i++) {
        S[tg * 4 + i][lane]      = acc[i][0];
        S[tg * 4 + i][lane + 32] = acc[i][1];
    }
    __syncthreads();

    float b0 = bias[lane], b1 = bias[lane + 32];
    for (int i = 0; i < 4; i++) {
        int t = tg * 4 + i;
        float s0 = S[t][lane], s1 = S[t][lane + 32];
        // softmax over 64 (2 per lane)
        float m = fmaxf(s0, s1);
        #pragma unroll
        for (int o = 16; o > 0; o >>= 1) m = fmaxf(m, __shfl_xor_sync(0xffffffffu, m, o));
        float e0 = expf(s0 - m), e1 = expf(s1 - m);
        float z = e0 + e1;
        #pragma unroll
        for (int o = 16; o > 0; o >>= 1) z += __shfl_xor_sync(0xffffffffu, z, o);
        float inv = 1.0f / z;
        float p0 = e0 * inv, p1 = e1 * inv;
        // selection key = prob + bias ; weight = prob (ROUTE_SCALE = 1)
        float k0v = p0 + b0, k1v = p1 + b1;
        int gt = tok0 + t;
        for (int r = 0; r < TOPK; r++) {
            float key, pv; int idx;
            if (k0v >= k1v) { key = k0v; pv = p0; idx = lane; }
            else            { key = k1v; pv = p1; idx = lane + 32; }
            #pragma unroll
            for (int o = 16; o > 0; o >>= 1) {
                float ok = __shfl_xor_sync(0xffffffffu, key, o);
                float op = __shfl_xor_sync(0xffffffffu, pv,  o);
                int   oi = __shfl_xor_sync(0xffffffffu, idx, o);
                if (ok > key || (ok == key && oi < idx)) { key = ok; pv = op; idx = oi; }
            }
            if (lane == 0) {
                g_eidx[gt * KSLOT + NSH + r] = idx + NSH;
                g_wt  [gt * KSLOT + NSH + r] = pv;   // * ROUTE_SCALE(=1)
                atomicAdd(&g_counts[idx + NSH], 1);
            }
            if (idx == lane)           k0v = -INFINITY;
            else if (idx == lane + 32) k1v = -INFINITY;
        }
        if (lane < NSH) {
            g_eidx[gt * KSLOT + lane] = lane;
            g_wt  [gt * KSLOT + lane] = 1.0f;
        }
    }
}

// ---------------- kernel 2: scan + tile build ----------------
__global__ void scan_kernel() {
    __shared__ int cnt[NEXP];
    int tid = threadIdx.x;
    if (tid < NEXP) cnt[tid] = (tid < NSH) ? NTOK : g_counts[tid];
    __syncthreads();
    if (tid == 0) {
        int off = 0, nt = 0;
        for (int e = 0; e < NEXP; e++) {
            g_offsets[e] = off;
            int c = cnt[e];
            for (int j = 0; j < c; j += TILE_M) {
                g_tiles[nt] = make_int4(e, off + j, min(TILE_M, c - j), 0);
                nt++;
            }
            off += c;
        }
        g_offsets[NEXP] = off;
        g_ntiles = nt;
    }
}

// ---------------- kernel 3: scatter token-slots into expert segments ----------------
__global__ void scatter_kernel() {
    int i = blockIdx.x * 256 + threadIdx.x;
    if (i >= NSLOT) return;
    int e = g_eidx[i];
    int pos = atomicAdd(&g_fill[e], 1);
    g_perm[g_offsets[e] + pos] = i;
}

// ---------------- kernel 4: grouped expert FFN ----------------
// grid MAXTILES x 256 threads; one 32-token tile per block
__global__ __launch_bounds__(256) void ffn_kernel(
    const float* __restrict__ x,  const float* __restrict__ w1,
    const float* __restrict__ w2, const float* __restrict__ w3)
{
    int bid = blockIdx.x;
    if (bid >= g_ntiles) return;
    int4 tl = g_tiles[bid];
    int e = tl.x, p0 = tl.y, m = tl.z;

    __shared__ int   toks[TILE_M];
    __shared__ float wts[TILE_M];
    __shared__ int   slots[TILE_M];
    __shared__ float Xs[TILE_M][32];
    __shared__ float W1t[INTER][33];
    __shared__ float W3t[INTER][33];
    __shared__ float Gsm[TILE_M][65];
    __shared__ float W2s[INTER][65];

    int tid  = threadIdx.x;
    int tg   = tid >> 5;      // warp id: tokens tg*4..tg*4+3
    int lane = tid & 31;      // inter cols lane, lane+32

    if (tid < TILE_M) {
        int i = (tid < m) ? g_perm[p0 + tid] : g_perm[p0];  // pad with token0
        slots[tid] = i;
        toks[tid]  = i >> 3;   // /KSLOT
        wts[tid]   = g_wt[i];
    }
    __syncthreads();

    const float* w1e = w1 + (size_t)e * DIMX * INTER;
    const float* w3e = w3 + (size_t)e * DIMX * INTER;

    float h1[4][2] = {}, h3[4][2] = {};

    for (int k0 = 0; k0 < DIMX; k0 += 32) {
        // X tile (gathered rows)
        {
            int r = tid >> 3;
            int c = (tid & 7) * 4;
            float4 v = *reinterpret_cast<const float4*>(&x[(size_t)toks[r] * DIMX + k0 + c]);
            Xs[r][c] = v.x; Xs[r][c+1] = v.y; Xs[r][c+2] = v.z; Xs[r][c+3] = v.w;
        }
        // W1,W3 transposed tiles [col][k]
        {
            int kk = tid >> 3;            // 0..31
            int c0 = (tid & 7) * 8;       // 0..56
            const float4* s1 = reinterpret_cast<const float4*>(&w1e[(size_t)(k0 + kk) * INTER + c0]);
            float4 a = s1[0], b = s1[1];
            W1t[c0+0][kk]=a.x; W1t[c0+1][kk]=a.y; W1t[c0+2][kk]=a.z; W1t[c0+3][kk]=a.w;
            W1t[c0+4][kk]=b.x; W1t[c0+5][kk]=b.y; W1t[c0+6][kk]=b.z; W1t[c0+7][kk]=b.w;
            const float4* s3 = reinterpret_cast<const float4*>(&w3e[(size_t)(k0 + kk) * INTER + c0]);
            float4 c = s3[0], d = s3[1];
            W3t[c0+0][kk]=c.x; W3t[c0+1][kk]=c.y; W3t[c0+2][kk]=c.z; W3t[c0+3][kk]=c.w;
            W3t[c0+4][kk]=d.x; W3t[c0+5][kk]=d.y; W3t[c0+6][kk]=d.z; W3t[c0+7][kk]=d.w;
        }
        __syncthreads();
        #pragma unroll
        for (int kk = 0; kk < 32; kk++) {
            float a0 = W1t[lane][kk],      a1 = W1t[lane + 32][kk];
            float c0 = W3t[lane][kk],      c1 = W3t[lane + 32][kk];
            #pragma unroll
            for (int i = 0; i < 4; i++) {
                float xv = Xs[tg * 4 + i][kk];
                h1[i][0] = fmaf(xv, a0, h1[i][0]);
                h1[i][1] = fmaf(xv, a1, h1[i][1]);
                h3[i][0] = fmaf(xv, c0, h3[i][0]);
                h3[i][1] = fmaf(xv, c1, h3[i][1]);
            }
        }
        __syncthreads();
    }

    // g = silu(h1) * h3
    #pragma unroll
    for (int i = 0; i < 4; i++) {
        #pragma unroll
        for (int j = 0; j < 2; j++) {
            float v = h1[i][j];
            float s = v / (1.0f + expf(-v));
            Gsm[tg * 4 + i][lane + j * 32] = s * h3[i][j];
        }
    }
    __syncthreads();

    const float* w2e = w2 + (size_t)e * INTER * DIMX;
    for (int d0 = 0; d0 < DIMX; d0 += 64) {
        // W2 tile [64 j][64 d]
        {
            int j  = tid >> 2;
            int c0 = (tid & 3) * 16;
            #pragma unroll
            for (int q = 0; q < 16; q += 4) {
                float4 v = *reinterpret_cast<const float4*>(&w2e[(size_t)j * DIMX + d0 + c0 + q]);
                W2s[j][c0+q+0]=v.x; W2s[j][c0+q+1]=v.y; W2s[j][c0+q+2]=v.z; W2s[j][c0+q+3]=v.w;
            }
        }
        __syncthreads();
        float o[4][2] = {};
        #pragma unroll
        for (int j = 0; j < INTER; j++) {
            float b0 = W2s[j][lane], b1 = W2s[j][lane + 32];
            #pragma unroll
            for (int i = 0; i < 4; i++) {
                float gv = Gsm[tg * 4 + i][j];
                o[i][0] = fmaf(gv, b0, o[i][0]);
                o[i][1] = fmaf(gv, b1, o[i][1]);
            }
        }
        #pragma unroll
        for (int i = 0; i < 4; i++) {
            int r = tg * 4 + i;
            if (r < m) {
                float wv = wts[r];
                size_t base = (size_t)slots[r] * DIMX + d0;
                g_slot_out[base + lane]      = o[i][0] * wv;
                g_slot_out[base + lane + 32] = o[i][1] * wv;
            }
        }
        __syncthreads();
    }
}

// ---------------- kernel 5: deterministic combine over 8 slots ----------------
__global__ void combine_kernel(float* __restrict__ out) {
    int i = blockIdx.x * 256 + threadIdx.x;   // token*512 + d
    if (i >= NTOK * DIMX) return;
    int t = i >> 9, d = i & (DIMX - 1);
    float s = 0.0f;
    #pragma unroll
    for (int sl = 0; sl < KSLOT; sl++)
        s += g_slot_out[((size_t)(t * KSLOT + sl)) * DIMX + d];
    out[i] = s;
}

// ---------------- launch ----------------
extern "C" void kernel_launch(void* const* d_in, const int* in_sizes, int n_in,
                              void* d_out, int out_size) {
    const float* x  = (const float*)d_in[0];
    const float* gw = (const float*)d_in[1];
    const float* gb = (const float*)d_in[2];
    const float* w1 = (const float*)d_in[3];
    const float* w2 = (const float*)d_in[4];
    const float* w3 = (const float*)d_in[5];
    float* out = (float*)d_out;

    zero_kernel<<<1, 128>>>();
    gate_kernel<<<NTOK / 32, 256>>>(x, gw, gb);
    scan_kernel<<<1, 128>>>();
    scatter_kernel<<<NSLOT / 256, 256>>>();
    ffn_kernel<<<MAXTILES, 256>>>(x, w1, w2, w3);
    combine_kernel<<<(NTOK * DIMX) / 256, 256>>>(out);
}

// round 2
// speedup vs baseline: 1.3384x; 1.3384x over previous
#include <cuda_runtime.h>
#include <cuda_bf16.h>
#include <math.h>

// ---------------- problem constants ----------------
#define DIMX     512
#define INTER    64
#define NSH      2
#define NROUTED  64
#define NEXP     66          // NSH + NROUTED
#define TOPK     6
#define KSLOT    8           // TOPK + NSH
#define NTOK     1024        // B*T
#define NSLOT    (NTOK * KSLOT)   // 8192
#define TILE_M   32
#define MAXTILES 320

typedef unsigned long long u64;

// ---------------- packed f32x2 helpers (Blackwell FFMA2 path) ----------------
__device__ __forceinline__ u64 ffma2(u64 a, u64 b, u64 c) {
    u64 d; asm("fma.rn.f32x2 %0, %1, %2, %3;" : "=l"(d) : "l"(a), "l"(b), "l"(c)); return d;
}
__device__ __forceinline__ u64 fadd2(u64 a, u64 b) {
    u64 d; asm("add.rn.f32x2 %0, %1, %2;" : "=l"(d) : "l"(a), "l"(b)); return d;
}
__device__ __forceinline__ u64 fpack(float lo, float hi) {
    u64 d; asm("mov.b64 %0, {%1, %2};" : "=l"(d) : "f"(lo), "f"(hi)); return d;
}
__device__ __forceinline__ u64 fdup(float s) { return fpack(s, s); }
__device__ __forceinline__ void funpack(u64 v, float& a, float& b) {
    asm("mov.b64 {%0, %1}, %2;" : "=f"(a), "=f"(b) : "l"(v));
}

// ---------------- device scratch (no allocs allowed) ----------------
__device__ int   g_eidx[NSLOT];        // expert id per token-slot
__device__ float g_wt[NSLOT];          // combine weight per token-slot
__device__ int   g_counts[NEXP];
__device__ int   g_fill[NEXP];
__device__ int   g_offsets[NEXP + 1];
__device__ int   g_perm[NSLOT];        // token-slot ids grouped by expert
__device__ int4  g_tiles[MAXTILES];    // (expert, segStart, len, 0)
__device__ int   g_ntiles;
__device__ float g_slot_out[(size_t)NSLOT * DIMX];  // 16 MB scratch

// ---------------- kernel 0: zero counters ----------------
__global__ void zero_kernel() {
    int t = threadIdx.x;
    if (t < NEXP) { g_counts[t] = 0; g_fill[t] = 0; }
}

// ---------------- kernel 1: gate (scores GEMM + softmax + topk) ----------------
__global__ __launch_bounds__(256) void gate_kernel(
    const float* __restrict__ x, const float* __restrict__ gw,
    const float* __restrict__ bias)
{
    __shared__ float Xs[32][32];
    __shared__ float Gs[32][65];
    __shared__ float S[32][66];

    int tid  = threadIdx.x;
    int tok0 = blockIdx.x * 32;
    int tg   = tid >> 5;       // warp id: 4 tokens each
    int lane = tid & 31;

    float acc[4][2] = {};

    for (int k0 = 0; k0 < DIMX; k0 += 32) {
        {
            int r = tid >> 3;
            int c = (tid & 7) * 4;
            float4 v = *reinterpret_cast<const float4*>(&x[(size_t)(tok0 + r) * DIMX + k0 + c]);
            Xs[r][c] = v.x; Xs[r][c+1] = v.y; Xs[r][c+2] = v.z; Xs[r][c+3] = v.w;
        }
        {
            int e  = tid >> 2;
            int kk = (tid & 3) * 8;
            float4 a = *reinterpret_cast<const float4*>(&gw[(size_t)e * DIMX + k0 + kk]);
            float4 b = *reinterpret_cast<const float4*>(&gw[(size_t)e * DIMX + k0 + kk + 4]);
            Gs[kk+0][e] = a.x; Gs[kk+1][e] = a.y; Gs[kk+2][e] = a.z; Gs[kk+3][e] = a.w;
            Gs[kk+4][e] = b.x; Gs[kk+5][e] = b.y; Gs[kk+6][e] = b.z; Gs[kk+7][e] = b.w;
        }
        __syncthreads();
        #pragma unroll
        for (int kk = 0; kk < 32; kk++) {
            float g0 = Gs[kk][lane], g1 = Gs[kk][lane + 32];
            #pragma unroll
            for (int i = 0; i < 4; i++) {
                float xv = Xs[tg * 4 + i][kk];
                acc[i][0] = fmaf(xv, g0, acc[i][0]);
                acc[i][1] = fmaf(xv, g1, acc[i][1]);
            }
        }
        __syncthreads();
    }
    #pragma unroll
    for (int i = 0; i < 4; i++) {
        S[tg * 4 + i][lane]      = acc[i][0];
        S[tg * 4 + i][lane + 32] = acc[i][1];
    }
    __syncthreads();

    float b0 = bias[lane], b1 = bias[lane + 32];
    for (int i = 0; i < 4; i++) {
        int t = tg * 4 + i;
        float s0 = S[t][lane], s1 = S[t][lane + 32];
        float m = fmaxf(s0, s1);
        #pragma unroll
        for (int o = 16; o > 0; o >>= 1) m = fmaxf(m, __shfl_xor_sync(0xffffffffu, m, o));
        float e0 = expf(s0 - m), e1 = expf(s1 - m);
        float z = e0 + e1;
        #pragma unroll
        for (int o = 16; o > 0; o >>= 1) z += __shfl_xor_sync(0xffffffffu, z, o);
        float inv = 1.0f / z;
        float p0 = e0 * inv, p1 = e1 * inv;
        float k0v = p0 + b0, k1v = p1 + b1;
        int gt = tok0 + t;
        for (int r = 0; r < TOPK; r++) {
            float key, pv; int idx;
            if (k0v >= k1v) { key = k0v; pv = p0; idx = lane; }
            else            { key = k1v; pv = p1; idx = lane + 32; }
            #pragma unroll
            for (int o = 16; o > 0; o >>= 1) {
                float ok = __shfl_xor_sync(0xffffffffu, key, o);
                float op = __shfl_xor_sync(0xffffffffu, pv,  o);
                int   oi = __shfl_xor_sync(0xffffffffu, idx, o);
                if (ok > key || (ok == key && oi < idx)) { key = ok; pv = op; idx = oi; }
            }
            if (lane == 0) {
                g_eidx[gt * KSLOT + NSH + r] = idx + NSH;
                g_wt  [gt * KSLOT + NSH + r] = pv;
                atomicAdd(&g_counts[idx + NSH], 1);
            }
            if (idx == lane)           k0v = -INFINITY;
            else if (idx == lane + 32) k1v = -INFINITY;
        }
        if (lane < NSH) {
            g_eidx[gt * KSLOT + lane] = lane;
            g_wt  [gt * KSLOT + lane] = 1.0f;
        }
    }
}

// ---------------- kernel 2: scan + tile build ----------------
__global__ void scan_kernel() {
    __shared__ int cnt[NEXP];
    int tid = threadIdx.x;
    if (tid < NEXP) cnt[tid] = (tid < NSH) ? NTOK : g_counts[tid];
    __syncthreads();
    if (tid == 0) {
        int off = 0, nt = 0;
        for (int e = 0; e < NEXP; e++) {
            g_offsets[e] = off;
            int c = cnt[e];
            for (int j = 0; j < c; j += TILE_M) {
                g_tiles[nt] = make_int4(e, off + j, min(TILE_M, c - j), 0);
                nt++;
            }
            off += c;
        }
        g_offsets[NEXP] = off;
        g_ntiles = nt;
    }
}

// ---------------- kernel 3: scatter token-slots into expert segments ----------------
__global__ void scatter_kernel() {
    int i = blockIdx.x * 256 + threadIdx.x;
    if (i >= NSLOT) return;
    int e = g_eidx[i];
    int pos = atomicAdd(&g_fill[e], 1);
    g_perm[g_offsets[e] + pos] = i;
}

// ---------------- kernel 4: grouped expert FFN (FFMA2 + k-split) ----------------
// 256 threads, one 32-token tile per block.
// h-stage: kg = wid>>1 (4 k-groups of 128 k each), tokg = wid&1 (16 tokens/warp as 8 pairs)
// W2-stage: jg = wid>>2 (2 j-groups of 32), tg2 = wid&3 (8 tokens/warp as 4 pairs)
__global__ __launch_bounds__(256, 2) void ffn_kernel(
    const float* __restrict__ x,  const float* __restrict__ w1,
    const float* __restrict__ w2, const float* __restrict__ w3)
{
    int bid = blockIdx.x;
    if (bid >= g_ntiles) return;
    int4 tl = g_tiles[bid];
    int e = tl.x, p0 = tl.y, m = tl.z;

    __shared__ __align__(16) float buf[8192];       // 32 KB, phase-aliased
    __shared__ __align__(16) float Gt[64][36];      // g transposed: [j][tok]
    __shared__ int   toks[TILE_M];
    __shared__ float wts[TILE_M];
    __shared__ int   slots[TILE_M];

    float* Xt  = buf;              // phase1: [32 k][36] transposed X tile
    float* W1s = buf + 1152;       // phase1: [32 k][64 j]
    float* W3s = buf + 3200;       // phase1: [32 k][64 j]
    u64*   P1a = (u64*)buf;        // phase2: [16 tp][64 j]  (kg1 partial)
    u64*   P3a = P1a + 1024;
    u64*   P1b = P1a + 2048;       // kg3 partial, then kg2+kg3
    u64*   P3b = P1a + 3072;
    float* W2s = buf;              // phase3: [64 j][64 d]
    u64*   OP  = (u64*)(buf + 4096); // phase3: [16 tp][64 d] (jg1 partial)

    int tid  = threadIdx.x;
    int wid  = tid >> 5;
    int lane = tid & 31;

    if (tid < TILE_M) {
        int i = (tid < m) ? g_perm[p0 + tid] : g_perm[p0];
        slots[tid] = i;
        toks[tid]  = i >> 3;
        wts[tid]   = g_wt[i];
    }
    __syncthreads();

    const float* w1e = w1 + (size_t)e * DIMX * INTER;
    const float* w3e = w3 + (size_t)e * DIMX * INTER;

    // ---- h-stage ----
    int kg    = wid >> 1;        // 0..3
    int tokg  = wid & 1;         // 0..1
    int tok0w = tokg * 16;

    u64 h1[8][2] = {};
    u64 h3[8][2] = {};

    for (int kb = 0; kb < 16; kb++) {
        int k0 = kb * 32;
        // stage X transposed: Xt[k][tok]
        {
            int r = tid >> 3;              // token 0..31
            int c = (tid & 7) * 4;         // k offset 0..28
            float4 v = *reinterpret_cast<const float4*>(&x[(size_t)toks[r] * DIMX + k0 + c]);
            Xt[(c+0)*36 + r] = v.x; Xt[(c+1)*36 + r] = v.y;
            Xt[(c+2)*36 + r] = v.z; Xt[(c+3)*36 + r] = v.w;
        }
        // stage W1/W3 row-major (global already [k][64])
        {
            int kk = tid >> 3;             // 0..31
            int c0 = (tid & 7) * 8;        // 0..56
            *reinterpret_cast<float4*>(&W1s[kk*64 + c0])
                = *reinterpret_cast<const float4*>(&w1e[(size_t)(k0+kk)*INTER + c0]);
            *reinterpret_cast<float4*>(&W1s[kk*64 + c0 + 4])
                = *reinterpret_cast<const float4*>(&w1e[(size_t)(k0+kk)*INTER + c0 + 4]);
            *reinterpret_cast<float4*>(&W3s[kk*64 + c0])
                = *reinterpret_cast<const float4*>(&w3e[(size_t)(k0+kk)*INTER + c0]);
            *reinterpret_cast<float4*>(&W3s[kk*64 + c0 + 4])
                = *reinterpret_cast<const float4*>(&w3e[(size_t)(k0+kk)*INTER + c0 + 4]);
        }
        __syncthreads();

        #pragma unroll
        for (int u = 0; u < 8; u++) {
            int kk = kg * 8 + u;
            u64 w1p = *reinterpret_cast<const u64*>(&W1s[kk*64 + 2*lane]);
            u64 w3p = *reinterpret_cast<const u64*>(&W3s[kk*64 + 2*lane]);
            float a0, a1, b0, b1;
            funpack(w1p, a0, a1); funpack(w3p, b0, b1);
            u64 d1a = fdup(a0), d1b = fdup(a1);
            u64 d3a = fdup(b0), d3b = fdup(b1);
            const float* xr = &Xt[kk*36 + tok0w];
            #pragma unroll
            for (int q = 0; q < 4; q++) {
                float4 xv = *reinterpret_cast<const float4*>(&xr[q*4]);
                u64 pA = fpack(xv.x, xv.y);
                u64 pB = fpack(xv.z, xv.w);
                h1[2*q  ][0] = ffma2(pA, d1a, h1[2*q  ][0]);
                h1[2*q  ][1] = ffma2(pA, d1b, h1[2*q  ][1]);
                h3[2*q  ][0] = ffma2(pA, d3a, h3[2*q  ][0]);
                h3[2*q  ][1] = ffma2(pA, d3b, h3[2*q  ][1]);
                h1[2*q+1][0] = ffma2(pB, d1a, h1[2*q+1][0]);
                h1[2*q+1][1] = ffma2(pB, d1b, h1[2*q+1][1]);
                h3[2*q+1][0] = ffma2(pB, d3a, h3[2*q+1][0]);
                h3[2*q+1][1] = ffma2(pB, d3b, h3[2*q+1][1]);
            }
        }
        __syncthreads();
    }

    // ---- k-group reduction: ((kg0+kg1)+(kg2+kg3)), fixed order ----
    if (kg == 1 || kg == 3) {
        u64* D1 = (kg == 1) ? P1a : P1b;
        u64* D3 = (kg == 1) ? P3a : P3b;
        #pragma unroll
        for (int p = 0; p < 8; p++) {
            int idx = (tokg*8 + p)*64 + 2*lane;
            D1[idx]   = h1[p][0]; D1[idx+1] = h1[p][1];
            D3[idx]   = h3[p][0]; D3[idx+1] = h3[p][1];
        }
    }
    __syncthreads();
    if (kg == 2) {
        #pragma unroll
        for (int p = 0; p < 8; p++) {
            int idx = (tokg*8 + p)*64 + 2*lane;
            P1b[idx]   = fadd2(h1[p][0], P1b[idx]);
            P1b[idx+1] = fadd2(h1[p][1], P1b[idx+1]);
            P3b[idx]   = fadd2(h3[p][0], P3b[idx]);
            P3b[idx+1] = fadd2(h3[p][1], P3b[idx+1]);
        }
    }
    __syncthreads();
    if (kg == 0) {
        #pragma unroll
        for (int p = 0; p < 8; p++) {
            #pragma unroll
            for (int ci = 0; ci < 2; ci++) {
                int idx = (tokg*8 + p)*64 + 2*lane + ci;
                u64 H1 = fadd2(fadd2(h1[p][ci], P1a[idx]), P1b[idx]);
                u64 H3 = fadd2(fadd2(h3[p][ci], P3a[idx]), P3b[idx]);
                float v0, v1, g0, g1;
                funpack(H1, v0, v1); funpack(H3, g0, g1);
                float s0 = (v0 / (1.0f + expf(-v0))) * g0;
                float s1 = (v1 / (1.0f + expf(-v1))) * g1;
                int c = 2*lane + ci;
                *reinterpret_cast<u64*>(&Gt[c][tok0w + 2*p]) = fpack(s0, s1);
            }
        }
    }
    __syncthreads();

    // ---- W2 stage ----
    const float* w2e = w2 + (size_t)e * INTER * DIMX;
    int jg  = wid >> 2;          // 0..1
    int tg2 = wid & 3;           // 0..3  -> tokens tg2*8..+7

    for (int db = 0; db < 8; db++) {
        // stage W2 tile [64 j][64 d]
        {
            int j  = tid >> 2;
            int c0 = (tid & 3) * 16;
            #pragma unroll
            for (int q = 0; q < 16; q += 4)
                *reinterpret_cast<float4*>(&W2s[j*64 + c0 + q])
                    = *reinterpret_cast<const float4*>(&w2e[(size_t)j*DIMX + db*64 + c0 + q]);
        }
        __syncthreads();

        u64 o[4][2] = {};
        #pragma unroll 4
        for (int jj = 0; jj < 32; jj++) {
            int j = jg*32 + jj;
            u64 w2p = *reinterpret_cast<const u64*>(&W2s[j*64 + 2*lane]);
            float b0, b1; funpack(w2p, b0, b1);
            u64 dwa = fdup(b0), dwb = fdup(b1);
            const float* gr = &Gt[j][tg2*8];
            float4 ga = *reinterpret_cast<const float4*>(&gr[0]);
            float4 gb = *reinterpret_cast<const float4*>(&gr[4]);
            u64 g0 = fpack(ga.x, ga.y), g1 = fpack(ga.z, ga.w);
            u64 g2 = fpack(gb.x, gb.y), g3 = fpack(gb.z, gb.w);
            o[0][0] = ffma2(g0, dwa, o[0][0]); o[0][1] = ffma2(g0, dwb, o[0][1]);
            o[1][0] = ffma2(g1, dwa, o[1][0]); o[1][1] = ffma2(g1, dwb, o[1][1]);
            o[2][0] = ffma2(g2, dwa, o[2][0]); o[2][1] = ffma2(g2, dwb, o[2][1]);
            o[3][0] = ffma2(g3, dwa, o[3][0]); o[3][1] = ffma2(g3, dwb, o[3][1]);
        }
        if (jg == 1) {
            #pragma unroll
            for (int p = 0; p < 4; p++) {
                int idx = (tg2*4 + p)*64 + 2*lane;
                OP[idx]   = o[p][0];
                OP[idx+1] = o[p][1];
            }
        }
        __syncthreads();
        if (jg == 0) {
            #pragma unroll
            for (int p = 0; p < 4; p++) {
                int t0 = tg2*8 + 2*p, t1 = t0 + 1;
                float wt0 = wts[t0], wt1 = wts[t1];
                size_t r0 = (size_t)slots[t0] * DIMX + db*64;
                size_t r1 = (size_t)slots[t1] * DIMX + db*64;
                #pragma unroll
                for (int ci = 0; ci < 2; ci++) {
                    int idx = (tg2*4 + p)*64 + 2*lane + ci;
                    u64 v = fadd2(o[p][ci], OP[idx]);
                    float v0, v1; funpack(v, v0, v1);
                    int c = 2*lane + ci;
                    if (t0 < m) g_slot_out[r0 + c] = v0 * wt0;
                    if (t1 < m) g_slot_out[r1 + c] = v1 * wt1;
                }
            }
        }
        __syncthreads();
    }
}

// ---------------- kernel 5: deterministic combine over 8 slots (float4) ----------------
__global__ void combine_kernel(float* __restrict__ out) {
    int i = blockIdx.x * 256 + threadIdx.x;    // vec4 index
    if (i >= NTOK * DIMX / 4) return;
    int t = i >> 7;                             // / (DIMX/4)
    int d4 = i & (DIMX/4 - 1);
    float4 s = make_float4(0.f, 0.f, 0.f, 0.f);
    #pragma unroll
    for (int sl = 0; sl < KSLOT; sl++) {
        const float4* p = reinterpret_cast<const float4*>(
            &g_slot_out[((size_t)(t * KSLOT + sl)) * DIMX]);
        float4 v = p[d4];
        s.x += v.x; s.y += v.y; s.z += v.z; s.w += v.w;
    }
    reinterpret_cast<float4*>(out)[i] = s;
}

// ---------------- launch ----------------
extern "C" void kernel_launch(void* const* d_in, const int* in_sizes, int n_in,
                              void* d_out, int out_size) {
    const float* x  = (const float*)d_in[0];
    const float* gw = (const float*)d_in[1];
    const float* gb = (const float*)d_in[2];
    const float* w1 = (const float*)d_in[3];
    const float* w2 = (const float*)d_in[4];
    const float* w3 = (const float*)d_in[5];
    float* out = (float*)d_out;

    zero_kernel<<<1, 128>>>();
    gate_kernel<<<NTOK / 32, 256>>>(x, gw, gb);
    scan_kernel<<<1, 128>>>();
    scatter_kernel<<<NSLOT / 256, 256>>>();
    ffn_kernel<<<MAXTILES, 256>>>(x, w1, w2, w3);
    combine_kernel<<<(NTOK * DIMX / 4) / 256, 256>>>(out);
}